// round 1
// baseline (speedup 1.0000x reference)
#include <cuda_runtime.h>
#include <cstddef>

#define TT 1024
#define BB 32
#define HH 512
#define GG 2048
#define NBLK 128
#define OUT1_ELEMS (TT*BB*HH)         // 16777216
#define BH (BB*HH)                    // 16384

// ---------------- device globals (scratch; no allocation allowed) -------------
__device__ float g_gi0[(size_t)TT * BB * GG];   // 256 MB: precomputed x @ w_ih0^T + b_ih0
__device__ float g_h0buf[2 * BH];               // double-buffered layer0 hidden
__device__ float g_h1buf[2 * BH];               // double-buffered layer1 hidden
__device__ unsigned g_bar;                      // barrier arrival counter
__device__ unsigned g_gen;                      // barrier generation

// swizzle: k -> (k&31)*16 + (k>>5); row stride 513 => conflict-free tiled reads
#define SW(k) ((((k) & 31) << 4) | ((k) >> 5))

// ======================= input-projection GEMM ===============================
// C[M=32768][N=2048] = A[M][512] * W[N][512]^T + bias;  C written to g_gi0
__global__ void __launch_bounds__(256) gemm_in2h(
    const float* __restrict__ A, const float* __restrict__ W,
    const float* __restrict__ bias)
{
    __shared__ float As[8][132];
    __shared__ float Bs[8][132];
    const int tid = threadIdx.x;
    const int n0 = blockIdx.x * 128;
    const int m0 = blockIdx.y * 128;
    const int tx = tid & 15, ty = tid >> 4;
    const int lrow = tid >> 1, lk4 = (tid & 1) * 4;
    const float* Ab = A + (size_t)(m0 + lrow) * 512 + lk4;
    const float* Wb = W + (size_t)(n0 + lrow) * 512 + lk4;

    float acc[8][8];
#pragma unroll
    for (int i = 0; i < 8; i++)
#pragma unroll
        for (int j = 0; j < 8; j++) acc[i][j] = 0.f;

    for (int k0 = 0; k0 < 512; k0 += 8) {
        float4 av = *(const float4*)(Ab + k0);
        float4 wv = *(const float4*)(Wb + k0);
        As[lk4 + 0][lrow] = av.x; As[lk4 + 1][lrow] = av.y;
        As[lk4 + 2][lrow] = av.z; As[lk4 + 3][lrow] = av.w;
        Bs[lk4 + 0][lrow] = wv.x; Bs[lk4 + 1][lrow] = wv.y;
        Bs[lk4 + 2][lrow] = wv.z; Bs[lk4 + 3][lrow] = wv.w;
        __syncthreads();
#pragma unroll
        for (int k = 0; k < 8; k++) {
            float a[8], b[8];
            *(float4*)&a[0] = *(const float4*)&As[k][ty * 8];
            *(float4*)&a[4] = *(const float4*)&As[k][ty * 8 + 4];
            *(float4*)&b[0] = *(const float4*)&Bs[k][tx * 8];
            *(float4*)&b[4] = *(const float4*)&Bs[k][tx * 8 + 4];
#pragma unroll
            for (int i = 0; i < 8; i++)
#pragma unroll
                for (int j = 0; j < 8; j++) acc[i][j] += a[i] * b[j];
        }
        __syncthreads();
    }

    float bv[8];
#pragma unroll
    for (int j = 0; j < 8; j++) bv[j] = bias[n0 + tx * 8 + j];
#pragma unroll
    for (int i = 0; i < 8; i++) {
        size_t row = (size_t)(m0 + ty * 8 + i);
        float* Crow = g_gi0 + row * 2048 + n0 + tx * 8;
#pragma unroll
        for (int j = 0; j < 8; j++) Crow[j] = acc[i][j] + bv[j];
    }
}

// ======================= persistent recurrence kernel ========================
__device__ __forceinline__ float sigf(float x) { return 1.f / (1.f + __expf(-x)); }

__device__ __forceinline__ void gridbar() {
    __syncthreads();
    if (threadIdx.x == 0) {
        __threadfence();
        unsigned g = *(volatile unsigned*)&g_gen;
        if (atomicAdd(&g_bar, 1u) == NBLK - 1) {
            g_bar = 0;
            __threadfence();
            *(volatile unsigned*)&g_gen = g + 1;
        } else {
            while (*(volatile unsigned*)&g_gen == g) { }
        }
    }
    __syncthreads();
}

__device__ __forceinline__ void stage_h(float* __restrict__ hs,
                                        const float* __restrict__ src, int tid) {
    // src: [32][512] contiguous -> hs: [32][513] swizzled
#pragma unroll 4
    for (int u4 = tid; u4 < 4096; u4 += 256) {
        int u = u4 << 2;
        int b = u >> 9, k = u & 511;
        float4 v = ((const float4*)src)[u4];
        float* hb = hs + b * 513;
        hb[SW(k)]     = v.x;
        hb[SW(k + 1)] = v.y;
        hb[SW(k + 2)] = v.z;
        hb[SW(k + 3)] = v.w;
    }
}

__device__ __forceinline__ void gemm_acc(const float* __restrict__ hs,
                                         const float* __restrict__ ws,
                                         int b0, int r0, int kc, float acc[8][4]) {
    const float* wp = ws + r0 * 513 + kc;
    const float* hp = hs + b0 * 513 + kc;
#pragma unroll 8
    for (int kk = 0; kk < 32; kk++) {
        int off = kk << 4;
        float w0 = wp[off], w1 = wp[off + 513], w2 = wp[off + 1026], w3 = wp[off + 1539];
#pragma unroll
        for (int i = 0; i < 8; i++) {
            float hv = hp[i * 513 + off];
            acc[i][0] += hv * w0;
            acc[i][1] += hv * w1;
            acc[i][2] += hv * w2;
            acc[i][3] += hv * w3;
        }
    }
}

__device__ __forceinline__ void reduce_combine(float acc[8][4], float* __restrict__ gsm,
                                               int kh, int kcl, int b0, int r0) {
#pragma unroll
    for (int i = 0; i < 8; i++)
#pragma unroll
        for (int j = 0; j < 4; j++) {
            float v = acc[i][j];
            v += __shfl_xor_sync(0xffffffffu, v, 1);
            v += __shfl_xor_sync(0xffffffffu, v, 2);
            v += __shfl_xor_sync(0xffffffffu, v, 4);
            acc[i][j] = v;
        }
    if (kh == 0) {
#pragma unroll
        for (int i = 0; i < 8; i++)
            if (i == kcl) {
#pragma unroll
                for (int j = 0; j < 4; j++) gsm[(r0 + j) * 32 + b0 + i] = acc[i][j];
            }
    }
    __syncthreads();
    if (kh == 1) {
#pragma unroll
        for (int i = 0; i < 8; i++)
            if (i == kcl) {
#pragma unroll
                for (int j = 0; j < 4; j++) gsm[(r0 + j) * 32 + b0 + i] += acc[i][j];
            }
    }
    __syncthreads();
}

__global__ void __launch_bounds__(256, 1) lstm_rec(
    const float* __restrict__ w_hh0, const float* __restrict__ b_hh0,
    const float* __restrict__ w_ih1, const float* __restrict__ w_hh1,
    const float* __restrict__ b_ih1, const float* __restrict__ b_hh1,
    const float* __restrict__ h0_in, const float* __restrict__ c0_in,
    float* __restrict__ dout)
{
    extern __shared__ float sm[];
    float* ws0  = sm;                 // 16*513 = 8208
    float* wsi1 = sm + 8208;
    float* wsh1 = sm + 16416;
    float* hs   = sm + 24624;         // 32*513 = 16416
    float* gsm  = sm + 41040;         // 16*32  = 512
    float* csm  = sm + 41552;         // 2*4*32 = 256

    const int tid = threadIdx.x;
    const int bid = blockIdx.x;
    const int J0 = bid << 2;

    // Stage this block's 16 weight rows per matrix (swizzled), once.
    for (int u = tid; u < 16 * 512; u += 256) {
        int r = u >> 9, k = u & 511;
        int gr = ((r >> 2) << 9) + J0 + (r & 3);  // global gate row g*512 + J0 + jl
        int d = r * 513 + SW(k);
        ws0[d]  = w_hh0[gr * 512 + k];
        wsi1[d] = w_ih1[gr * 512 + k];
        wsh1[d] = w_hh1[gr * 512 + k];
    }
    // Initialize hidden buffers at parity 1 (read by step 0).
    {
        int u = (bid << 8) + tid;   // 0..32767 covers h0_in (2,32,512)
        if (u < BH) g_h0buf[BH + u] = h0_in[u];
        else        g_h1buf[u]      = h0_in[u];   // BH + (u - BH) == u
    }
    // Cell state in smem, block-local: csm[layer*128 + jl*32 + b]
    {
        int l = tid >> 7, jl = (tid >> 5) & 3, b = tid & 31;
        csm[tid] = c0_in[(l << 14) + (b << 9) + J0 + jl];
    }

    const int lane = tid & 31, warp = tid >> 5;
    const int rg = warp >> 1, kh = warp & 1;
    const int bg = lane >> 3, kcl = lane & 7;
    const int kc = (kh << 3) + kcl;
    const int b0 = bg << 3, r0 = rg << 2;

    // loop-invariant biases for the elementwise threads
    float bI0 = 0, bF0 = 0, bG0 = 0, bO0 = 0;
    float bI1 = 0, bF1 = 0, bG1 = 0, bO1 = 0;
    if (tid < 128) {
        int jl = tid >> 5, Jj = J0 + jl;
        bI0 = b_hh0[Jj];        bF0 = b_hh0[512 + Jj];
        bG0 = b_hh0[1024 + Jj]; bO0 = b_hh0[1536 + Jj];
        bI1 = b_ih1[Jj] + b_hh1[Jj];
        bF1 = b_ih1[512 + Jj] + b_hh1[512 + Jj];
        bG1 = b_ih1[1024 + Jj] + b_hh1[1024 + Jj];
        bO1 = b_ih1[1536 + Jj] + b_hh1[1536 + Jj];
    }

    gridbar();

    float accv[8][4];

    for (int t = 0; t < TT; t++) {
        const int p = t & 1, q = p ^ 1;

        // prefetch gi0[t] for elementwise (hides L2/HBM latency behind the GEMM)
        float giI = 0, giF = 0, giG = 0, giO = 0;
        if (tid < 128) {
            int jl = tid >> 5, b = tid & 31, Jj = J0 + jl;
            const float* gi = g_gi0 + ((size_t)t << 16) + ((size_t)b << 11);
            giI = gi[Jj]; giF = gi[512 + Jj]; giG = gi[1024 + Jj]; giO = gi[1536 + Jj];
        }

        // ---------------- phase 0: layer 0 ----------------
        stage_h(hs, g_h0buf + (q << 14), tid);
        __syncthreads();
#pragma unroll
        for (int i = 0; i < 8; i++)
#pragma unroll
            for (int j = 0; j < 4; j++) accv[i][j] = 0.f;
        gemm_acc(hs, ws0, b0, r0, kc, accv);
        reduce_combine(accv, gsm, kh, kcl, b0, r0);

        if (tid < 128) {
            int jl = tid >> 5, b = tid & 31, Jj = J0 + jl;
            float gI = giI + gsm[jl * 32 + b] + bI0;
            float gF = giF + gsm[(4 + jl) * 32 + b] + bF0;
            float gG = giG + gsm[(8 + jl) * 32 + b] + bG0;
            float gO = giO + gsm[(12 + jl) * 32 + b] + bO0;
            float iv = sigf(gI), fv = sigf(gF), gv = tanhf(gG), ov = sigf(gO);
            float c = fv * csm[jl * 32 + b] + iv * gv;
            csm[jl * 32 + b] = c;
            float h = ov * tanhf(c);
            g_h0buf[(p << 14) + (b << 9) + Jj] = h;
            if (t == TT - 1) {
                dout[OUT1_ELEMS + (b << 9) + Jj] = h;                 // h_n[0]
                dout[OUT1_ELEMS + 2 * BH + (b << 9) + Jj] = c;        // c_n[0]
            }
        }

        gridbar();

        // ---------------- phase 1: layer 1 ----------------
        stage_h(hs, g_h0buf + (p << 14), tid);   // x1 = layer0 output at t
        __syncthreads();
#pragma unroll
        for (int i = 0; i < 8; i++)
#pragma unroll
            for (int j = 0; j < 4; j++) accv[i][j] = 0.f;
        gemm_acc(hs, wsi1, b0, r0, kc, accv);
        __syncthreads();
        stage_h(hs, g_h1buf + (q << 14), tid);   // h1_prev
        __syncthreads();
        gemm_acc(hs, wsh1, b0, r0, kc, accv);
        reduce_combine(accv, gsm, kh, kcl, b0, r0);

        if (tid < 128) {
            int jl = tid >> 5, b = tid & 31, Jj = J0 + jl;
            float gI = gsm[jl * 32 + b] + bI1;
            float gF = gsm[(4 + jl) * 32 + b] + bF1;
            float gG = gsm[(8 + jl) * 32 + b] + bG1;
            float gO = gsm[(12 + jl) * 32 + b] + bO1;
            float iv = sigf(gI), fv = sigf(gF), gv = tanhf(gG), ov = sigf(gO);
            float c = fv * csm[128 + jl * 32 + b] + iv * gv;
            csm[128 + jl * 32 + b] = c;
            float h = ov * tanhf(c);
            g_h1buf[(p << 14) + (b << 9) + Jj] = h;
            dout[((size_t)t << 14) + (b << 9) + Jj] = h;              // out1[t]
            if (t == TT - 1) {
                dout[OUT1_ELEMS + BH + (b << 9) + Jj] = h;            // h_n[1]
                dout[OUT1_ELEMS + 2 * BH + BH + (b << 9) + Jj] = c;   // c_n[1]
            }
        }
        // no grid barrier needed here: phase0(t+1) touches no buffer phase1(t)
        // writes, and phase1(t+1) is separated by the next gridbar.
    }
}

// ============================== launcher =====================================
extern "C" void kernel_launch(void* const* d_in, const int* in_sizes, int n_in,
                              void* d_out, int out_size) {
    const float* x     = (const float*)d_in[0];
    const float* w_ih0 = (const float*)d_in[1];
    const float* w_hh0 = (const float*)d_in[2];
    const float* b_ih0 = (const float*)d_in[3];
    const float* b_hh0 = (const float*)d_in[4];
    const float* w_ih1 = (const float*)d_in[5];
    const float* w_hh1 = (const float*)d_in[6];
    const float* b_ih1 = (const float*)d_in[7];
    const float* b_hh1 = (const float*)d_in[8];
    const float* h0    = (const float*)d_in[9];
    const float* c0    = (const float*)d_in[10];
    float* out = (float*)d_out;

    const int smem_bytes = 41808 * 4;  // 167232 B
    cudaFuncSetAttribute(lstm_rec, cudaFuncAttributeMaxDynamicSharedMemorySize,
                         smem_bytes);

    // 1) gi0 = x @ w_ih0^T + b_ih0  (fully parallel)
    gemm_in2h<<<dim3(16, 256), 256>>>(x, w_ih0, b_ih0);

    // 2) persistent fused 2-layer recurrence
    lstm_rec<<<NBLK, 256, smem_bytes>>>(w_hh0, b_hh0, w_ih1, w_hh1, b_ih1, b_hh1,
                                        h0, c0, out);
}